// round 3
// baseline (speedup 1.0000x reference)
#include <cuda_runtime.h>
#include <cuda_bf16.h>
#include <stdint.h>

#define N_TOT 8192
#define FDIM  64
#define OD    64

// ---------------- scratch (__device__ globals; no allocations allowed) ----------------
static __device__ __align__(16) __nv_bfloat16 g_Gt[OD * N_TOT];      // G^T = (F@W2^T)^T bf16, [o][k]
static __device__ __align__(16) float g_FW1 [N_TOT * OD];            // features @ W1^T (fp32 exact)
static __device__ __align__(16) float g_part[2 * N_TOT * OD];        // split-K partials of adj@G
static __device__ float g_degp[2 * N_TOT];                           // split-K deg partials

// ---------------- helpers ----------------
__device__ __forceinline__ uint32_t smem_u32(const void* p) {
    uint32_t a;
    asm("{ .reg .u64 t; cvta.to.shared.u64 t, %1; cvt.u32.u64 %0, t; }" : "=r"(a) : "l"(p));
    return a;
}

// pack two fp32 -> bf16x2 (x = lo = first arg)
__device__ __forceinline__ uint32_t packbf2(float lo, float hi) {
    uint32_t d;
    asm("cvt.rn.bf16x2.f32 %0, %1, %2;" : "=r"(d) : "f"(hi), "f"(lo));
    return d;
}

#define LDSM_X4(R, ADDR) \
    asm volatile("ldmatrix.sync.aligned.m8n8.x4.shared.b16 {%0,%1,%2,%3}, [%4];" \
        : "=r"((R)[0]), "=r"((R)[1]), "=r"((R)[2]), "=r"((R)[3]) : "r"(ADDR))

__device__ __forceinline__ void mma_bf16(float* c, const uint32_t* a, uint32_t b0, uint32_t b1) {
    asm volatile(
        "mma.sync.aligned.m16n8k16.row.col.f32.bf16.bf16.f32 "
        "{%0,%1,%2,%3}, {%4,%5,%6,%7}, {%8,%9}, {%0,%1,%2,%3};"
        : "+f"(c[0]), "+f"(c[1]), "+f"(c[2]), "+f"(c[3])
        : "r"(a[0]), "r"(a[1]), "r"(a[2]), "r"(a[3]), "r"(b0), "r"(b1));
}

// ---------------- prep: G^T = (F@W2^T)^T (bf16), FW1 = F@W1^T (fp32) ----------------
__global__ void __launch_bounds__(256) sage_prep(const float* __restrict__ feat,
                                                 const float* __restrict__ W) {
    __shared__ float Ws[64 * 132];   // W[o][0..127], row stride 132
    __shared__ float Fp[2112];       // F tile [32][66]  then  G staging [64][33]
    const int t  = threadIdx.x;
    const int ib = blockIdx.x;       // 256 blocks x 32 feature rows

    #pragma unroll
    for (int j = 0; j < 32; j++) {
        int idx = t + 256 * j;                                   // 8192 W elems
        Ws[(idx >> 7) * 132 + (idx & 127)] = W[idx];
    }
    #pragma unroll
    for (int j = 0; j < 8; j++) {
        int idx = t + 256 * j;                                   // 2048 F elems
        Fp[(idx >> 6) * 66 + (idx & 63)] = feat[(size_t)ib * 2048 + idx];
    }
    __syncthreads();

    const int il = t >> 3;           // local row 0..31
    const int og = t & 7;            // o = og + 8*oi
    float g[8], fw[8];
    #pragma unroll
    for (int oi = 0; oi < 8; oi++) { g[oi] = 0.f; fw[oi] = 0.f; }

    for (int f = 0; f < 64; f++) {
        float fv = Fp[il * 66 + f];
        #pragma unroll
        for (int oi = 0; oi < 8; oi++) {
            int o = og + 8 * oi;
            fw[oi] = fmaf(fv, Ws[o * 132 + f],      fw[oi]);
            g [oi] = fmaf(fv, Ws[o * 132 + 64 + f], g [oi]);
        }
    }
    const int gi = ib * 32 + il;
    #pragma unroll
    for (int oi = 0; oi < 8; oi++)
        g_FW1[(size_t)gi * 64 + og + 8 * oi] = fw[oi];

    __syncthreads();
    #pragma unroll
    for (int oi = 0; oi < 8; oi++)
        Fp[(og + 8 * oi) * 33 + il] = g[oi];
    __syncthreads();

    #pragma unroll
    for (int j = 0; j < 8; j++) {
        int idx = t + 256 * j;                                   // 2048 G elems
        int o = idx >> 5, i2 = idx & 31;
        g_Gt[(size_t)o * N_TOT + ib * 32 + i2] = __float2bfloat16_rn(Fp[o * 33 + i2]);
    }
}

// ---------------- main GEMM: part[ks] = adj[:, ks-half] @ G[ks-half], fused rowsum ----------------
#define BM 128
#define BK 64
#define NSTAGE 64                        // 4096 / 64
#define A_OFF 0                          // A tile: 128 rows x 128 B (bf16 k-major, xor-swizzled)
#define B_OFF 16384                      // B tile: 64 n-rows x 128 B
#define BUF_BYTES 24576
#define SMEM_MAIN 49152

__global__ void __launch_bounds__(256, 1) sage_main(const float* __restrict__ adj) {
    extern __shared__ char smem[];
    const uint32_t sb = smem_u32(smem);
    const int t = threadIdx.x, w = t >> 5, lane = t & 31;
    const int ks = blockIdx.y;
    const size_t row0 = (size_t)blockIdx.x * BM;
    const int kbase = ks * 4096;

    // producer mapping
    const int r = t >> 1, h = t & 1;                 // A: row r, 32-float half h
    const float* aptr = adj + (row0 + r) * (size_t)N_TOT + kbase + 32 * h;
    const int bo = t >> 2, q = t & 3;                // B: n-row bo, 16-bf16 quarter q
    const __nv_bfloat16* gptr = g_Gt + (size_t)bo * N_TOT + kbase + 16 * q;

    float deg = 0.f;
    float acc[8][4];
    #pragma unroll
    for (int nt = 0; nt < 8; nt++)
        #pragma unroll
        for (int i = 0; i < 4; i++) acc[nt][i] = 0.f;

    float4 va[8];
    uint4  vb[2];

    auto ldg = [&](int s) {
        const float4* pa = (const float4*)(aptr + (size_t)s * BK);
        #pragma unroll
        for (int j = 0; j < 8; j++) va[j] = pa[j];
        const uint4* pb = (const uint4*)(gptr + (size_t)s * BK);
        vb[0] = pb[0]; vb[1] = pb[1];
    };

    auto sts = [&](int s) {
        char* base = smem + (s & 1) * BUF_BYTES;
        #pragma unroll
        for (int j = 0; j < 8; j++) deg += (va[j].x + va[j].y) + (va[j].z + va[j].w);
        #pragma unroll
        for (int j2 = 0; j2 < 4; j2++) {
            uint4 P;
            P.x = packbf2(va[2 * j2].x,     va[2 * j2].y);
            P.y = packbf2(va[2 * j2].z,     va[2 * j2].w);
            P.z = packbf2(va[2 * j2 + 1].x, va[2 * j2 + 1].y);
            P.w = packbf2(va[2 * j2 + 1].z, va[2 * j2 + 1].w);
            int c = h * 4 + j2;                       // 16B chunk index 0..7
            *(uint4*)(base + A_OFF + r * 128 + ((c ^ (r & 7)) << 4)) = P;
        }
        #pragma unroll
        for (int j = 0; j < 2; j++) {
            int c = q * 2 + j;
            *(uint4*)(base + B_OFF + bo * 128 + ((c ^ (bo & 7)) << 4)) = vb[j];
        }
    };

    auto compute = [&](int s) {
        const uint32_t abase = sb + (s & 1) * BUF_BYTES + A_OFF;
        const uint32_t bbase = sb + (s & 1) * BUF_BYTES + B_OFF;
        // A fragments: 4 k16-steps, warp rows [w*16, w*16+16)
        uint32_t af[4][4];
        const int arow = w * 16 + (lane & 15);
        const uint32_t a0 = abase + arow * 128;
        #pragma unroll
        for (int k = 0; k < 4; k++) {
            uint32_t addr = a0 + (((k * 2 + (lane >> 4)) ^ (lane & 7)) << 4);
            LDSM_X4(af[k], addr);
        }
        const int brow = lane & 7;
        const int bch  = (lane >> 3) & 3;
        #pragma unroll
        for (int nt = 0; nt < 8; nt++) {
            int n = nt * 8 + brow;
            uint32_t bb = bbase + n * 128;
            uint32_t b0[4], b1[4];
            LDSM_X4(b0, bb + ((bch       ^ (n & 7)) << 4));   // k 0..31
            LDSM_X4(b1, bb + (((4 + bch) ^ (n & 7)) << 4));   // k 32..63
            mma_bf16(acc[nt], af[0], b0[0], b0[1]);
            mma_bf16(acc[nt], af[1], b0[2], b0[3]);
            mma_bf16(acc[nt], af[2], b1[0], b1[1]);
            mma_bf16(acc[nt], af[3], b1[2], b1[3]);
        }
    };

    ldg(0);
    sts(0);
    __syncthreads();

    for (int s = 0; s < NSTAGE; s++) {
        if (s + 1 < NSTAGE) ldg(s + 1);      // issue global loads early
        compute(s);                           // mma on current buffer
        if (s + 1 < NSTAGE) sts(s + 1);      // fill other buffer
        __syncthreads();
    }

    // epilogue: write split-K partials
    {
        const size_t m0 = row0 + (size_t)w * 16 + (lane >> 2);
        float* dst = g_part + (size_t)ks * N_TOT * OD;
        #pragma unroll
        for (int nt = 0; nt < 8; nt++) {
            int n = nt * 8 + 2 * (lane & 3);
            *(float2*)(dst + m0 * OD + n)       = make_float2(acc[nt][0], acc[nt][1]);
            *(float2*)(dst + (m0 + 8) * OD + n) = make_float2(acc[nt][2], acc[nt][3]);
        }
    }

    // deg partial: threads (r,0) and (r,1) are lanes t, t^1 in same warp
    float dsum = deg + __shfl_xor_sync(0xffffffffu, deg, 1);
    if (h == 0) g_degp[ks * N_TOT + row0 + r] = dsum;
}

// ---------------- combine: out = FW1 + (p0 + p1) / (d0 + d1 + 1) ----------------
__global__ void __launch_bounds__(256) sage_combine(float* __restrict__ out) {
    int idx = blockIdx.x * 256 + threadIdx.x;       // 524288 total
    int i = idx >> 6;
    float d = g_degp[i] + g_degp[N_TOT + i] + 1.0f;
    out[idx] = g_FW1[idx] + (g_part[idx] + g_part[idx + N_TOT * OD]) / d;
}

// ---------------- launch ----------------
extern "C" void kernel_launch(void* const* d_in, const int* in_sizes, int n_in,
                              void* d_out, int out_size) {
    const float* adj  = (const float*)d_in[0];
    const float* feat = (const float*)d_in[1];
    const float* W    = (const float*)d_in[2];
    float* out = (float*)d_out;

    cudaFuncSetAttribute(sage_main, cudaFuncAttributeMaxDynamicSharedMemorySize, SMEM_MAIN);

    sage_prep<<<256, 256>>>(feat, W);
    sage_main<<<dim3(64, 2), 256, SMEM_MAIN>>>(adj);
    sage_combine<<<2048, 256>>>(out);
}

// round 6
// speedup vs baseline: 1.3995x; 1.3995x over previous
#include <cuda_runtime.h>
#include <cuda_bf16.h>
#include <stdint.h>

#define N_TOT 8192
#define FDIM  64
#define OD    64
#define KSPLIT 4

// ---------------- scratch (__device__ globals; no allocations allowed) ----------------
static __device__ __align__(16) __nv_bfloat16 g_Gt[OD * N_TOT];        // G^T = (F@W2^T)^T bf16, [o][k]
static __device__ __align__(16) float g_FW1 [N_TOT * OD];              // features @ W1^T (fp32 exact)
static __device__ __align__(16) float g_part[KSPLIT * N_TOT * OD];     // split-K partials of adj@G
static __device__ float g_degp[KSPLIT * N_TOT];                        // split-K deg partials

// ---------------- helpers ----------------
__device__ __forceinline__ uint32_t smem_u32(const void* p) {
    uint32_t a;
    asm("{ .reg .u64 t; cvta.to.shared.u64 t, %1; cvt.u32.u64 %0, t; }" : "=r"(a) : "l"(p));
    return a;
}

// pack two fp32 -> bf16x2 (x = lo = first arg)
__device__ __forceinline__ uint32_t packbf2(float lo, float hi) {
    uint32_t d;
    asm("cvt.rn.bf16x2.f32 %0, %1, %2;" : "=r"(d) : "f"(hi), "f"(lo));
    return d;
}

#define LDSM_X4(R, ADDR) \
    asm volatile("ldmatrix.sync.aligned.m8n8.x4.shared.b16 {%0,%1,%2,%3}, [%4];" \
        : "=r"((R)[0]), "=r"((R)[1]), "=r"((R)[2]), "=r"((R)[3]) : "r"(ADDR))
#define LDSM_X2(R, ADDR) \
    asm volatile("ldmatrix.sync.aligned.m8n8.x2.shared.b16 {%0,%1}, [%2];" \
        : "=r"((R)[0]), "=r"((R)[1]) : "r"(ADDR))

__device__ __forceinline__ void mma_bf16(float* c, const uint32_t* a, uint32_t b0, uint32_t b1) {
    asm volatile(
        "mma.sync.aligned.m16n8k16.row.col.f32.bf16.bf16.f32 "
        "{%0,%1,%2,%3}, {%4,%5,%6,%7}, {%8,%9}, {%0,%1,%2,%3};"
        : "+f"(c[0]), "+f"(c[1]), "+f"(c[2]), "+f"(c[3])
        : "r"(a[0]), "r"(a[1]), "r"(a[2]), "r"(a[3]), "r"(b0), "r"(b1));
}

// ---------------- prep v2: G^T = (F@W2^T)^T (bf16), FW1 = F@W1^T (fp32) ----------------
// 128 blocks x 64 rows. Thread: 2 rows x 8 outs, float4 over k. FMA-bound.
#define PREP_SMEM ((64 * 132 + 64 * 68) * 4)
__global__ void __launch_bounds__(256) sage_prep(const float* __restrict__ feat,
                                                 const float* __restrict__ W) {
    extern __shared__ float ps[];
    float* Ws = ps;              // [64][132]  W rows (o-major), padded
    float* Fp = ps + 64 * 132;   // [64][68]   F tile, then G staging [64 o][64 row]
    const int t  = threadIdx.x;
    const int rb = blockIdx.x * 64;

    #pragma unroll
    for (int j = 0; j < 32; j++) {                       // 8192 W floats
        int idx = t + 256 * j;
        Ws[(idx >> 7) * 132 + (idx & 127)] = W[idx];
    }
    #pragma unroll
    for (int j = 0; j < 16; j++) {                       // 4096 F floats
        int idx = t + 256 * j;
        Fp[(idx >> 6) * 68 + (idx & 63)] = feat[(size_t)rb * 64 + idx];
    }
    __syncthreads();

    const int rg = t >> 3;        // rows 2rg, 2rg+1 (0..31)
    const int og = t & 7;         // o = og + 8*oi
    float fw[2][8], gg[2][8];
    #pragma unroll
    for (int rr = 0; rr < 2; rr++)
        #pragma unroll
        for (int oi = 0; oi < 8; oi++) { fw[rr][oi] = 0.f; gg[rr][oi] = 0.f; }

    #pragma unroll 4
    for (int f = 0; f < 64; f += 4) {
        float4 a0 = *(const float4*)&Fp[(2 * rg)     * 68 + f];
        float4 a1 = *(const float4*)&Fp[(2 * rg + 1) * 68 + f];
        #pragma unroll
        for (int oi = 0; oi < 8; oi++) {
            int o = og + 8 * oi;
            float4 w1 = *(const float4*)&Ws[o * 132 + f];
            float4 w2 = *(const float4*)&Ws[o * 132 + 64 + f];
            fw[0][oi] = fmaf(a0.x, w1.x, fmaf(a0.y, w1.y, fmaf(a0.z, w1.z, fmaf(a0.w, w1.w, fw[0][oi]))));
            fw[1][oi] = fmaf(a1.x, w1.x, fmaf(a1.y, w1.y, fmaf(a1.z, w1.z, fmaf(a1.w, w1.w, fw[1][oi]))));
            gg[0][oi] = fmaf(a0.x, w2.x, fmaf(a0.y, w2.y, fmaf(a0.z, w2.z, fmaf(a0.w, w2.w, gg[0][oi]))));
            gg[1][oi] = fmaf(a1.x, w2.x, fmaf(a1.y, w2.y, fmaf(a1.z, w2.z, fmaf(a1.w, w2.w, gg[1][oi]))));
        }
    }

    #pragma unroll
    for (int rr = 0; rr < 2; rr++)
        #pragma unroll
        for (int oi = 0; oi < 8; oi++)
            g_FW1[(size_t)(rb + 2 * rg + rr) * OD + og + 8 * oi] = fw[rr][oi];

    __syncthreads();                 // Fp reads done; reuse as G staging [o][row]
    #pragma unroll
    for (int rr = 0; rr < 2; rr++)
        #pragma unroll
        for (int oi = 0; oi < 8; oi++)
            Fp[(og + 8 * oi) * 68 + 2 * rg + rr] = gg[rr][oi];
    __syncthreads();

    #pragma unroll
    for (int j = 0; j < 16; j++) {                       // 4096 G elems
        int idx = t + 256 * j;
        int o = idx >> 6, row = idx & 63;
        g_Gt[(size_t)o * N_TOT + rb + row] = __float2bfloat16_rn(Fp[o * 68 + row]);
    }
}

// ---------------- main GEMM: part[ks] = adj[:, ks-quarter] @ G, fused rowsum ----------------
#define BM 128
#define BK 64
#define NSTAGE ((N_TOT / KSPLIT) / BK)   // 32
#define A_OFF 0                          // A tile: 128 rows x 128 B (bf16 k-major, xor-swizzled)
#define B_OFF 16384                      // B tile: 64 n-rows x 128 B
#define BUF_BYTES 24576
#define SMEM_MAIN 49152

__global__ void __launch_bounds__(256, 2) sage_main(const float* __restrict__ adj) {
    extern __shared__ char smem[];
    const uint32_t sb = smem_u32(smem);
    const int t = threadIdx.x, w = t >> 5, lane = t & 31;
    const int mw = w >> 1, nw = w & 1;          // 4 M-warps x 2 N-warps
    const int ks = blockIdx.y;
    const size_t row0 = (size_t)blockIdx.x * BM;
    const int kbase = ks * (N_TOT / KSPLIT);

    // producer mapping
    const int r = t >> 1, h = t & 1;            // A: row r, 32-float half h
    const float* aptr = adj + (row0 + r) * (size_t)N_TOT + kbase + 32 * h;
    const int bo = t >> 2, q = t & 3;           // B: n-row bo, 16-bf16 quarter q
    const __nv_bfloat16* gptr = g_Gt + (size_t)bo * N_TOT + kbase + 16 * q;

    float deg = 0.f;
    float acc[2][4][4];                          // [mtile][ntile][frag]
    #pragma unroll
    for (int mt = 0; mt < 2; mt++)
        #pragma unroll
        for (int nt = 0; nt < 4; nt++)
            #pragma unroll
            for (int i = 0; i < 4; i++) acc[mt][nt][i] = 0.f;

    float4 va[8];
    uint4  vb[2];

    auto ldg = [&](int s) {
        const float4* pa = (const float4*)(aptr + (size_t)s * BK);
        #pragma unroll
        for (int j = 0; j < 8; j++) va[j] = pa[j];
        const uint4* pb = (const uint4*)(gptr + (size_t)s * BK);
        vb[0] = pb[0]; vb[1] = pb[1];
    };

    auto sts = [&](int s) {
        char* base = smem + (s & 1) * BUF_BYTES;
        #pragma unroll
        for (int j = 0; j < 8; j++) deg += (va[j].x + va[j].y) + (va[j].z + va[j].w);
        #pragma unroll
        for (int j2 = 0; j2 < 4; j2++) {
            uint4 P;
            P.x = packbf2(va[2 * j2].x,     va[2 * j2].y);
            P.y = packbf2(va[2 * j2].z,     va[2 * j2].w);
            P.z = packbf2(va[2 * j2 + 1].x, va[2 * j2 + 1].y);
            P.w = packbf2(va[2 * j2 + 1].z, va[2 * j2 + 1].w);
            int c = h * 4 + j2;                  // 16B chunk index 0..7
            *(uint4*)(base + A_OFF + r * 128 + ((c ^ (r & 7)) << 4)) = P;
        }
        #pragma unroll
        for (int j = 0; j < 2; j++) {
            int c = q * 2 + j;
            *(uint4*)(base + B_OFF + bo * 128 + ((c ^ (bo & 7)) << 4)) = vb[j];
        }
    };

    auto compute = [&](int s) {
        const uint32_t abase = sb + (s & 1) * BUF_BYTES + A_OFF;
        const uint32_t bbase = sb + (s & 1) * BUF_BYTES + B_OFF;
        const int arow0 = mw * 32 + (lane & 15);
        const int bn    = nw * 32 + (lane & 7);       // lanes 0..15 used by LDSM_X2
        const int bhalf = (lane >> 3) & 1;            // selects k-chunk within pair
        #pragma unroll
        for (int k = 0; k < 4; k++) {                 // k16 steps
            uint32_t af0[4], af1[4];
            uint32_t achk = ((k * 2 + (lane >> 4)) ^ (arow0 & 7)) << 4;
            uint32_t achk1 = ((k * 2 + (lane >> 4)) ^ ((arow0 + 16) & 7)) << 4;
            LDSM_X4(af0, abase + arow0 * 128 + achk);
            LDSM_X4(af1, abase + (arow0 + 16) * 128 + achk1);
            #pragma unroll
            for (int nt = 0; nt < 4; nt++) {
                int n = bn + nt * 8;
                uint32_t bf[2];
                uint32_t bchk = ((k * 2 + bhalf) ^ (n & 7)) << 4;
                LDSM_X2(bf, bbase + n * 128 + bchk);
                mma_bf16(acc[0][nt], af0, bf[0], bf[1]);
                mma_bf16(acc[1][nt], af1, bf[0], bf[1]);
            }
        }
    };

    ldg(0);
    sts(0);
    __syncthreads();

    for (int s = 0; s < NSTAGE; s++) {
        if (s + 1 < NSTAGE) ldg(s + 1);      // issue global loads early
        compute(s);                           // mma on current buffer
        if (s + 1 < NSTAGE) sts(s + 1);      // fill other buffer
        __syncthreads();
    }

    // epilogue: write split-K partials
    {
        float* dst = g_part + (size_t)ks * N_TOT * OD;
        #pragma unroll
        for (int mt = 0; mt < 2; mt++) {
            size_t m0 = row0 + (size_t)mw * 32 + mt * 16 + (lane >> 2);
            #pragma unroll
            for (int nt = 0; nt < 4; nt++) {
                int n = nw * 32 + nt * 8 + 2 * (lane & 3);
                *(float2*)(dst + m0 * OD + n)       = make_float2(acc[mt][nt][0], acc[mt][nt][1]);
                *(float2*)(dst + (m0 + 8) * OD + n) = make_float2(acc[mt][nt][2], acc[mt][nt][3]);
            }
        }
    }

    // deg partial: threads (r,0) and (r,1) are adjacent lanes in same warp
    float dsum = deg + __shfl_xor_sync(0xffffffffu, deg, 1);
    if (h == 0) g_degp[ks * N_TOT + row0 + r] = dsum;
}

// ---------------- combine: out = FW1 + (sum p) / (sum d + 1) ----------------
__global__ void __launch_bounds__(256) sage_combine(float* __restrict__ out) {
    int idx = blockIdx.x * 256 + threadIdx.x;       // 524288 total
    int i = idx >> 6;
    float d = g_degp[i] + g_degp[N_TOT + i] + g_degp[2 * N_TOT + i] + g_degp[3 * N_TOT + i] + 1.0f;
    float p = g_part[idx] + g_part[idx + N_TOT * OD]
            + g_part[idx + 2 * N_TOT * OD] + g_part[idx + 3 * N_TOT * OD];
    out[idx] = g_FW1[idx] + p / d;
}

// ---------------- launch ----------------
extern "C" void kernel_launch(void* const* d_in, const int* in_sizes, int n_in,
                              void* d_out, int out_size) {
    const float* adj  = (const float*)d_in[0];
    const float* feat = (const float*)d_in[1];
    const float* W    = (const float*)d_in[2];
    float* out = (float*)d_out;

    cudaFuncSetAttribute(sage_prep, cudaFuncAttributeMaxDynamicSharedMemorySize, PREP_SMEM);
    cudaFuncSetAttribute(sage_main, cudaFuncAttributeMaxDynamicSharedMemorySize, SMEM_MAIN);

    sage_prep<<<128, 256, PREP_SMEM>>>(feat, W);
    sage_main<<<dim3(64, KSPLIT), 256, SMEM_MAIN>>>(adj);
    sage_combine<<<2048, 256>>>(out);
}

// round 8
// speedup vs baseline: 1.5413x; 1.1013x over previous
#include <cuda_runtime.h>
#include <cuda_bf16.h>
#include <stdint.h>

#define N_TOT 8192
#define FDIM  64
#define OD    64
#define KSPLIT 4

// ---------------- scratch (__device__ globals; no allocations allowed) ----------------
static __device__ __align__(16) __nv_bfloat16 g_Gt[OD * N_TOT];        // G^T = (F@W2^T)^T bf16, [o][k]
static __device__ __align__(16) float g_FW1 [N_TOT * OD];              // features @ W1^T (fp32 exact)
static __device__ __align__(16) float g_part[KSPLIT * N_TOT * OD];     // split-K partials of adj@G
static __device__ float g_degp[KSPLIT * N_TOT];                        // split-K deg partials

// ---------------- helpers ----------------
__device__ __forceinline__ uint32_t smem_u32(const void* p) {
    uint32_t a;
    asm("{ .reg .u64 t; cvta.to.shared.u64 t, %1; cvt.u32.u64 %0, t; }" : "=r"(a) : "l"(p));
    return a;
}

// pack two fp32 -> bf16x2 (x = lo = first arg)
__device__ __forceinline__ uint32_t packbf2(float lo, float hi) {
    uint32_t d;
    asm("cvt.rn.bf16x2.f32 %0, %1, %2;" : "=r"(d) : "f"(hi), "f"(lo));
    return d;
}

#define CP_ASYNC16(dst_u32, src_ptr) \
    asm volatile("cp.async.cg.shared.global [%0], [%1], 16;" :: "r"(dst_u32), "l"(src_ptr))
#define CP_COMMIT() asm volatile("cp.async.commit_group;" ::: "memory")
#define CP_WAIT(n)  asm volatile("cp.async.wait_group %0;" :: "n"(n) : "memory")

#define LDSM_X2(R, ADDR) \
    asm volatile("ldmatrix.sync.aligned.m8n8.x2.shared.b16 {%0,%1}, [%2];" \
        : "=r"((R)[0]), "=r"((R)[1]) : "r"(ADDR))

__device__ __forceinline__ void mma_bf16(float* c, const uint32_t* a, uint32_t b0, uint32_t b1) {
    asm volatile(
        "mma.sync.aligned.m16n8k16.row.col.f32.bf16.bf16.f32 "
        "{%0,%1,%2,%3}, {%4,%5,%6,%7}, {%8,%9}, {%0,%1,%2,%3};"
        : "+f"(c[0]), "+f"(c[1]), "+f"(c[2]), "+f"(c[3])
        : "r"(a[0]), "r"(a[1]), "r"(a[2]), "r"(a[3]), "r"(b0), "r"(b1));
}

// ---------------- prep v3: G^T = (F@W2^T)^T (bf16), FW1 = F@W1^T (fp32) ----------------
// 256 blocks x 32 rows. Thread: 1 row x 8 outs, float4 over k. FMA-bound, high occ.
#define PREP_SMEM ((64 * 132 + 32 * 68 + 64 * 36) * 4)
__global__ void __launch_bounds__(256) sage_prep(const float* __restrict__ feat,
                                                 const float* __restrict__ W) {
    extern __shared__ float ps[];
    float* Ws = ps;                       // [64][132]  W rows (o-major), padded
    float* Fp = ps + 64 * 132;            // [32][68]   F tile
    float* Gs = ps + 64 * 132 + 32 * 68;  // [64][36]   G staging [o][row]
    const int t  = threadIdx.x;
    const int rb = blockIdx.x * 32;

    #pragma unroll
    for (int j = 0; j < 8; j++) {                        // 2048 float4 of W
        int i4 = t + 256 * j;
        int o = i4 >> 5, c4 = i4 & 31;
        *(float4*)&Ws[o * 132 + c4 * 4] = *(const float4*)&W[i4 * 4];
    }
    #pragma unroll
    for (int j = 0; j < 2; j++) {                        // 512 float4 of F
        int i4 = t + 256 * j;
        int r = i4 >> 4, c4 = i4 & 15;
        *(float4*)&Fp[r * 68 + c4 * 4] = *(const float4*)&feat[(size_t)rb * 64 + i4 * 4];
    }
    __syncthreads();

    const int row = t >> 3;       // 0..31
    const int og  = t & 7;        // o = og + 8*oi
    float fw[8], gg[8];
    #pragma unroll
    for (int oi = 0; oi < 8; oi++) { fw[oi] = 0.f; gg[oi] = 0.f; }

    #pragma unroll 4
    for (int f = 0; f < 64; f += 4) {
        float4 a0 = *(const float4*)&Fp[row * 68 + f];
        #pragma unroll
        for (int oi = 0; oi < 8; oi++) {
            int o = og + 8 * oi;
            float4 w1 = *(const float4*)&Ws[o * 132 + f];
            float4 w2 = *(const float4*)&Ws[o * 132 + 64 + f];
            fw[oi] = fmaf(a0.x, w1.x, fmaf(a0.y, w1.y, fmaf(a0.z, w1.z, fmaf(a0.w, w1.w, fw[oi]))));
            gg[oi] = fmaf(a0.x, w2.x, fmaf(a0.y, w2.y, fmaf(a0.z, w2.z, fmaf(a0.w, w2.w, gg[oi]))));
        }
    }

    #pragma unroll
    for (int oi = 0; oi < 8; oi++)
        g_FW1[(size_t)(rb + row) * OD + og + 8 * oi] = fw[oi];

    #pragma unroll
    for (int oi = 0; oi < 8; oi++)
        Gs[(og + 8 * oi) * 36 + row] = gg[oi];
    __syncthreads();

    #pragma unroll
    for (int j = 0; j < 8; j++) {                        // 2048 G elems
        int idx = t + 256 * j;
        int o = idx >> 5, r2 = idx & 31;
        g_Gt[(size_t)o * N_TOT + rb + r2] = __float2bfloat16_rn(Gs[o * 36 + r2]);
    }
}

// ---------------- main GEMM: cp.async 4-stage, A kept fp32 in smem ----------------
#define BM 128
#define BK 32
#define NSTAGE ((N_TOT / KSPLIT) / BK)   // 64
#define NPIPE 4
#define A_PITCH 160                       // bytes per A row (32 fp32 + 32B pad)
#define A_BYTES (BM * A_PITCH)            // 20480
#define B_PITCH 80                        // bytes per B n-row (32 bf16 + 16B pad)
#define B_OFF   A_BYTES
#define STAGE_BYTES (A_BYTES + OD * B_PITCH)   // 25600
#define SMEM_MAIN (NPIPE * STAGE_BYTES)        // 102400

__global__ void __launch_bounds__(256, 2) sage_main(const float* __restrict__ adj) {
    extern __shared__ char smem[];
    const uint32_t sb = smem_u32(smem);
    const int t = threadIdx.x, w = t >> 5, lane = t & 31;
    const int mw = w >> 1, nw = w & 1;          // 4 M-warps x 2 N-warps
    const int ks = blockIdx.y;
    const size_t row0 = (size_t)blockIdx.x * BM;
    const int kbase = ks * (N_TOT / KSPLIT);

    // producer chunk mappings (16B chunks)
    // A: 1024 chunks/stage -> 4 per thread: j = 4t+i, r = j>>3, c = j&7
    // B: 256 chunks/stage  -> 1 per thread: o = t>>2, c = t&3
    const int aj0 = t * 4;
    const int bo = t >> 2, bc = t & 3;

    float acc[2][4][4];
    #pragma unroll
    for (int mt = 0; mt < 2; mt++)
        #pragma unroll
        for (int nt = 0; nt < 4; nt++)
            #pragma unroll
            for (int i = 0; i < 4; i++) acc[mt][nt][i] = 0.f;
    float dg[4] = {0.f, 0.f, 0.f, 0.f};

    auto issue_stage = [&](int s) {
        const uint32_t base = sb + (s & (NPIPE - 1)) * STAGE_BYTES;
        #pragma unroll
        for (int i = 0; i < 4; i++) {
            int j = aj0 + i, r = j >> 3, c = j & 7;
            const float* src = adj + (row0 + r) * (size_t)N_TOT + kbase + s * BK + c * 4;
            CP_ASYNC16(base + r * A_PITCH + c * 16, src);
        }
        const __nv_bfloat16* bsrc = g_Gt + (size_t)bo * N_TOT + kbase + s * BK + bc * 8;
        CP_ASYNC16(base + B_OFF + bo * B_PITCH + bc * 16, bsrc);
        CP_COMMIT();
    };

    auto consume = [&](int s) {
        const uint32_t base = sb + (s & (NPIPE - 1)) * STAGE_BYTES;
        const float* As = (const float*)(smem + (s & (NPIPE - 1)) * STAGE_BYTES);
        const int lq = lane & 3, lr = lane >> 2;
        #pragma unroll
        for (int k = 0; k < 2; k++) {                    // two k16 steps
            uint32_t bf[4][2];
            #pragma unroll
            for (int nt = 0; nt < 4; nt++) {
                uint32_t baddr = base + B_OFF
                    + (nw * 32 + nt * 8 + (lane & 7)) * B_PITCH
                    + (2 * k + ((lane >> 3) & 1)) * 16;
                LDSM_X2(bf[nt], baddr);
            }
            #pragma unroll
            for (int mt = 0; mt < 2; mt++) {
                int r0 = mw * 32 + mt * 16 + lr;
                int c0 = k * 16 + lq * 2;
                float2 p00 = *(const float2*)&As[(r0    ) * 40 + c0    ];
                float2 p10 = *(const float2*)&As[(r0 + 8) * 40 + c0    ];
                float2 p01 = *(const float2*)&As[(r0    ) * 40 + c0 + 8];
                float2 p11 = *(const float2*)&As[(r0 + 8) * 40 + c0 + 8];
                if (nw == 0) {
                    dg[mt * 2 + 0] += (p00.x + p00.y) + (p01.x + p01.y);
                    dg[mt * 2 + 1] += (p10.x + p10.y) + (p11.x + p11.y);
                }
                uint32_t af[4];
                af[0] = packbf2(p00.x, p00.y);
                af[1] = packbf2(p10.x, p10.y);
                af[2] = packbf2(p01.x, p01.y);
                af[3] = packbf2(p11.x, p11.y);
                #pragma unroll
                for (int nt = 0; nt < 4; nt++)
                    mma_bf16(acc[mt][nt], af, bf[nt][0], bf[nt][1]);
            }
        }
    };

    // prologue: fill 3 stages
    issue_stage(0);
    issue_stage(1);
    issue_stage(2);

    for (int s = 0; s < NSTAGE; s++) {
        if (s < NSTAGE - 2)      { CP_WAIT(2); }
        else if (s == NSTAGE - 2){ CP_WAIT(1); }
        else                     { CP_WAIT(0); }
        __syncthreads();
        consume(s);
        if (s + 3 < NSTAGE) issue_stage(s + 3);
        __syncthreads();
    }

    // epilogue: write split-K partials
    {
        float* dst = g_part + (size_t)ks * N_TOT * OD;
        #pragma unroll
        for (int mt = 0; mt < 2; mt++) {
            size_t m0 = row0 + (size_t)mw * 32 + mt * 16 + (lane >> 2);
            #pragma unroll
            for (int nt = 0; nt < 4; nt++) {
                int n = nw * 32 + nt * 8 + 2 * (lane & 3);
                *(float2*)(dst + m0 * OD + n)       = make_float2(acc[mt][nt][0], acc[mt][nt][1]);
                *(float2*)(dst + (m0 + 8) * OD + n) = make_float2(acc[mt][nt][2], acc[mt][nt][3]);
            }
        }
    }

    // deg: reduce over the 4 lanes sharing a row (xor 1, 2), nw==0 warps only
    if (nw == 0) {
        #pragma unroll
        for (int i = 0; i < 4; i++) {
            dg[i] += __shfl_xor_sync(0xffffffffu, dg[i], 1);
            dg[i] += __shfl_xor_sync(0xffffffffu, dg[i], 2);
        }
        if ((lane & 3) == 0) {
            int r = lane >> 2;                     // 0..7
            size_t b = (size_t)ks * N_TOT + row0 + mw * 32;
            g_degp[b + r]      = dg[0];
            g_degp[b + r + 8]  = dg[1];
            g_degp[b + r + 16] = dg[2];
            g_degp[b + r + 24] = dg[3];
        }
    }
}

// ---------------- combine: out = FW1 + (sum p) / (sum d + 1) ----------------
__global__ void __launch_bounds__(256) sage_combine(float* __restrict__ out) {
    int idx = blockIdx.x * 256 + threadIdx.x;       // 524288 total
    int i = idx >> 6;
    float d = g_degp[i] + g_degp[N_TOT + i] + g_degp[2 * N_TOT + i] + g_degp[3 * N_TOT + i] + 1.0f;
    float p = g_part[idx] + g_part[idx + N_TOT * OD]
            + g_part[idx + 2 * N_TOT * OD] + g_part[idx + 3 * N_TOT * OD];
    out[idx] = g_FW1[idx] + p / d;
}

// ---------------- launch ----------------
extern "C" void kernel_launch(void* const* d_in, const int* in_sizes, int n_in,
                              void* d_out, int out_size) {
    const float* adj  = (const float*)d_in[0];
    const float* feat = (const float*)d_in[1];
    const float* W    = (const float*)d_in[2];
    float* out = (float*)d_out;

    cudaFuncSetAttribute(sage_prep, cudaFuncAttributeMaxDynamicSharedMemorySize, PREP_SMEM);
    cudaFuncSetAttribute(sage_main, cudaFuncAttributeMaxDynamicSharedMemorySize, SMEM_MAIN);

    sage_prep<<<256, 256, PREP_SMEM>>>(feat, W);
    sage_main<<<dim3(64, KSPLIT), 256, SMEM_MAIN>>>(adj);
    sage_combine<<<2048, 256>>>(out);
}